// round 16
// baseline (speedup 1.0000x reference)
#include <cuda_runtime.h>
#include <cuda_bf16.h>
#include <math.h>

#define N_TOK 2048
#define H_DIM 1024
#define V_DIM 50304
#define K_CL  16
#define C_CL  3144
#define MTILE 256
#define NTILE 128
#define NCT   25            // 24 full n-tiles + 72-col tail
#define VTAIL 72
#define KC    32            // K per chunk
#define NCH   (H_DIM / KC)  // 32 chunks
#define ASTR  40            // A smem row stride (bf16): 32 + 8 pad
#define BSTR  136           // B smem k-row stride (bf16): 128 + 8 pad
#define ASZ   (MTILE * ASTR)            // bf16 per A buffer (10240)
#define BSZ   (KC * BSTR)               // bf16 per B buffer (4352)
#define TAIL_DSMEM ((2 * ASZ + 2 * BSZ) * 2)   // 58368 B
#define HSTR  1028
#define HEAD_SMEM (K_CL * HSTR * 4)     // 65792 B

__device__ float g_head[N_TOK];
__device__ int   g_within[N_TOK];
__device__ int   g_cnt[K_CL];            // zeroed at load + reset by combine_kernel
__device__ int   g_list[K_CL * N_TOK];
__device__ float g_pm[N_TOK * NCT];
__device__ float g_ps[N_TOK * NCT];
__device__ float g_tz[N_TOK];
__device__ __nv_bfloat16 g_xbf[K_CL * 256 * H_DIM];  // 16 clusters x 256 rows, 8MB

__device__ __forceinline__ unsigned smem_u32(const void* p) {
    unsigned a;
    asm("{ .reg .u64 t; cvta.to.shared.u64 t, %1; cvt.u32.u64 %0, t; }"
        : "=r"(a) : "l"(p));
    return a;
}
__device__ __forceinline__ void cpa16(unsigned dst, const void* src) {
    asm volatile("cp.async.cg.shared.global [%0], [%1], 16;"
                 :: "r"(dst), "l"(src) : "memory");
}
#define CP_COMMIT() asm volatile("cp.async.commit_group;" ::: "memory")
#define CP_WAIT0()  asm volatile("cp.async.wait_group 0;" ::: "memory")
__device__ __forceinline__ void lse_update(float &m, float &s, float z) {
    if (z <= m) { s += expf(z - m); }
    else        { s = s * expf(m - z) + 1.f; m = z; }
}

// ---------------- Kernel A: head log-softmax + bucketing + bf16 x-scatter ----------------
__global__ void __launch_bounds__(256)
head_kernel(const float* __restrict__ x, const int* __restrict__ y,
            const int* __restrict__ y_pos, const float* __restrict__ cw)
{
    extern __shared__ float cwt[];               // [16][HSTR]
    const int tid = threadIdx.x, lane = tid & 31, wid = tid >> 5;

    // one-time transpose: cw[h][k] -> cwt[k][h] (stride HSTR breaks bank collisions)
    const float4* cw4 = reinterpret_cast<const float4*>(cw);
    #pragma unroll
    for (int it = 0; it < 16; ++it) {
        const int j = it * 256 + tid;            // float4 index in [0,4096)
        const float4 v = __ldg(cw4 + j);
        const int h = j >> 2, k0 = (j & 3) * 4;
        cwt[(k0 + 0) * HSTR + h] = v.x;
        cwt[(k0 + 1) * HSTR + h] = v.y;
        cwt[(k0 + 2) * HSTR + h] = v.z;
        cwt[(k0 + 3) * HSTR + h] = v.w;
    }
    __syncthreads();

    const int n = blockIdx.x * 8 + wid;
    const float* xr = x + (size_t)n * H_DIM;
    const float4* xr4 = reinterpret_cast<const float4*>(xr);

    float a[K_CL];
    #pragma unroll
    for (int kk = 0; kk < K_CL; ++kk) a[kk] = 0.f;

    #pragma unroll 2
    for (int qb = 0; qb < 8; ++qb) {
        const int h0 = qb * 128 + lane * 4;
        const float4 xv = __ldg(xr4 + (h0 >> 2));
        #pragma unroll
        for (int kk = 0; kk < K_CL; ++kk) {
            const float4 w = *reinterpret_cast<const float4*>(&cwt[kk * HSTR + h0]);
            a[kk] = fmaf(xv.x, w.x, fmaf(xv.y, w.y, fmaf(xv.z, w.z,
                     fmaf(xv.w, w.w, a[kk]))));
        }
    }
    #pragma unroll
    for (int kk = 0; kk < K_CL; ++kk)
        #pragma unroll
        for (int off = 16; off; off >>= 1)
            a[kk] += __shfl_xor_sync(0xffffffffu, a[kk], off);

    const int yp = y_pos[n];
    int p = 0;
    if (lane == 0) {
        float m = a[0];
        #pragma unroll
        for (int kk = 1; kk < K_CL; ++kk) m = fmaxf(m, a[kk]);
        float e = 0.f;
        #pragma unroll
        for (int kk = 0; kk < K_CL; ++kk) e += expf(a[kk] - m);
        float s = a[0];
        #pragma unroll
        for (int kk = 0; kk < K_CL; ++kk) if (kk == yp) s = a[kk];
        g_head[n]   = s - m - logf(e);
        g_within[n] = y[n] % C_CL;            // token_in_pos_id[i][v] == v % C
        p = atomicAdd(&g_cnt[yp], 1);
        g_list[yp * N_TOK + p] = n;           // order nondeterministic; output order-invariant
    }
    p = __shfl_sync(0xffffffffu, p, 0);

    if (p < 256) {
        __nv_bfloat16* dst = g_xbf + (size_t)(yp * 256 + p) * H_DIM;
        #pragma unroll
        for (int q = 0; q < 4; ++q) {
            const int h8 = q * 256 + lane * 8;
            const float4 v0 = __ldg(xr4 + (h8 >> 2));
            const float4 v1 = __ldg(xr4 + (h8 >> 2) + 1);
            __nv_bfloat162 p0 = __floats2bfloat162_rn(v0.x, v0.y);
            __nv_bfloat162 p1 = __floats2bfloat162_rn(v0.z, v0.w);
            __nv_bfloat162 p2 = __floats2bfloat162_rn(v1.x, v1.y);
            __nv_bfloat162 p3 = __floats2bfloat162_rn(v1.z, v1.w);
            uint4 u;
            u.x = *reinterpret_cast<unsigned*>(&p0);
            u.y = *reinterpret_cast<unsigned*>(&p1);
            u.z = *reinterpret_cast<unsigned*>(&p2);
            u.w = *reinterpret_cast<unsigned*>(&p3);
            *reinterpret_cast<uint4*>(dst + h8) = u;
        }
    }
}

// ---------------- Kernel C: bf16 mma.sync tail GEMM, M=256 ----------------
// grid (K_CL, NCT). CTA: M=256 (whole cluster), N=128, K=1024.
// 512 threads, 16 warps = 8(M) x 2(N), warp tile 32x64. B loaded ONCE per (k,nt).
// Warps with no valid rows skip ldmatrix+MMA entirely (warp-uniform).
__global__ void __launch_bounds__(512, 1)
tail_mma_kernel(const float* __restrict__ logits)
{
    extern __shared__ char dsm[];
    __nv_bfloat16* Asb = reinterpret_cast<__nv_bfloat16*>(dsm);            // [2][ASZ]
    __nv_bfloat16* Bsb = reinterpret_cast<__nv_bfloat16*>(dsm + 4 * ASZ); // [2][BSZ]
    __shared__ int   s_idx[MTILE], s_wil[MTILE];
    __shared__ float s_pm[2][MTILE], s_ps[2][MTILE], s_ptz[2][MTILE];
    __shared__ int   s_pf[2][MTILE];

    const int k  = blockIdx.x;
    const int nt = blockIdx.y;
    const int cnt = g_cnt[k];
    const int tid = threadIdx.x, wid = tid >> 5, lane = tid & 31;
    const int vc  = (nt == NCT - 1) ? VTAIL : NTILE;
    const int ntb = nt * NTILE;
    const int rows_valid = min(MTILE, cnt);
    const float* gW = logits + (size_t)k * C_CL + ntb;
    const __nv_bfloat16* gx = g_xbf + (size_t)(k * 256) * H_DIM;

    if (tid < MTILE) {
        const int idx = (tid < cnt) ? g_list[k * N_TOK + tid] : -1;
        s_idx[tid] = idx;
        s_wil[tid] = (idx >= 0) ? (g_within[idx] - ntb) : (int)0xC0000000;
    }
    __syncthreads();

    // A cp.async: 1024 x 16B per chunk / 512 thr = 2 each (rows tid>>2, +128)
    const int arow0 = tid >> 2, aseg = tid & 3;
    const unsigned aoff = arow0 * 80 + aseg * 16;
    const __nv_bfloat16* asrc = gx + (size_t)arow0 * H_DIM + aseg * 8;

    // B: 32 rows x 128 cols / 512 thr = 2 float4 each (rows tid>>5, +16)
    const int bc4 = lane * 4;
    const int br0 = tid >> 5;                    // 0..15
    const bool bvalid = bc4 < vc;
    const float* bbase = gW + (size_t)br0 * V_DIM + bc4;
    const unsigned bsts0 = br0 * BSTR + bc4;

    {
        const unsigned ab = smem_u32(Asb);
        cpa16(ab + aoff, asrc);
        cpa16(ab + aoff + 128 * 80, asrc + 128 * H_DIM);
        CP_COMMIT();
    }
    float4 rb[2];
    #pragma unroll
    for (int it = 0; it < 2; ++it)
        rb[it] = bvalid ? *reinterpret_cast<const float4*>(bbase + (size_t)it * 16 * V_DIM)
                        : make_float4(0.f, 0.f, 0.f, 0.f);

    float d[2][8][4];
    #pragma unroll
    for (int mb = 0; mb < 2; ++mb)
        #pragma unroll
        for (int nb = 0; nb < 8; ++nb)
            #pragma unroll
            for (int j = 0; j < 4; ++j) d[mb][nb][j] = 0.f;

    const int wm = wid >> 1, wn = wid & 1;       // wm 0..7, wn 0..1
    const bool mbv[2] = { wm * 32 < rows_valid, wm * 32 + 16 < rows_valid };
    const bool wactive = mbv[0];                 // mbv[1] implies mbv[0]

    for (int c = 0; c < NCH; ++c) {
        const int buf = c & 1;
        #pragma unroll
        for (int it = 0; it < 2; ++it) {
            __nv_bfloat162 p0 = __floats2bfloat162_rn(rb[it].x, rb[it].y);
            __nv_bfloat162 p1 = __floats2bfloat162_rn(rb[it].z, rb[it].w);
            uint2 u;
            u.x = *reinterpret_cast<unsigned*>(&p0);
            u.y = *reinterpret_cast<unsigned*>(&p1);
            *reinterpret_cast<uint2*>(&Bsb[buf * BSZ + bsts0 + it * 16 * BSTR]) = u;
        }
        CP_WAIT0();
        __syncthreads();

        if (c + 1 < NCH) {
            const unsigned ab = smem_u32(Asb) + (buf ^ 1) * (2 * ASZ);
            const __nv_bfloat16* as = asrc + (c + 1) * KC;
            cpa16(ab + aoff, as);
            cpa16(ab + aoff + 128 * 80, as + 128 * H_DIM);
            CP_COMMIT();
            const float* bs = bbase + (size_t)(c + 1) * KC * V_DIM;
            #pragma unroll
            for (int it = 0; it < 2; ++it)
                rb[it] = bvalid ? *reinterpret_cast<const float4*>(bs + (size_t)it * 16 * V_DIM)
                                : make_float4(0.f, 0.f, 0.f, 0.f);
        }

        if (wactive) {
            const __nv_bfloat16* Ab = Asb + buf * (2 * ASZ) / 2;  // buf*ASZ
            #pragma unroll
            for (int ks = 0; ks < 2; ++ks) {
                const int k0 = ks * 16;
                unsigned a[2][4];
                #pragma unroll
                for (int mb = 0; mb < 2; ++mb) {
                    if (mbv[mb]) {
                        const unsigned addr = smem_u32(
                            &Ab[(wm * 32 + mb * 16 + (lane & 15)) * ASTR + k0 + ((lane >> 4) << 3)]);
                        asm volatile("ldmatrix.sync.aligned.m8n8.x4.shared.b16 {%0,%1,%2,%3}, [%4];"
                            : "=r"(a[mb][0]), "=r"(a[mb][1]), "=r"(a[mb][2]), "=r"(a[mb][3])
                            : "r"(addr));
                    }
                }
                #pragma unroll
                for (int np = 0; np < 4; ++np) {
                    unsigned b[4];
                    const unsigned addr = smem_u32(
                        &Bsb[buf * BSZ + (k0 + (lane & 15)) * BSTR + wn * 64 + np * 16 + ((lane >> 4) << 3)]);
                    asm volatile("ldmatrix.sync.aligned.m8n8.x4.trans.shared.b16 {%0,%1,%2,%3}, [%4];"
                        : "=r"(b[0]), "=r"(b[1]), "=r"(b[2]), "=r"(b[3]) : "r"(addr));
                    #pragma unroll
                    for (int mb = 0; mb < 2; ++mb) {
                        if (mbv[mb]) {
                            asm volatile(
                                "mma.sync.aligned.m16n8k16.row.col.f32.bf16.bf16.f32 "
                                "{%0,%1,%2,%3}, {%4,%5,%6,%7}, {%8,%9}, {%0,%1,%2,%3};"
                                : "+f"(d[mb][2*np][0]), "+f"(d[mb][2*np][1]),
                                  "+f"(d[mb][2*np][2]), "+f"(d[mb][2*np][3])
                                : "r"(a[mb][0]), "r"(a[mb][1]), "r"(a[mb][2]), "r"(a[mb][3]),
                                  "r"(b[0]), "r"(b[1]));
                            asm volatile(
                                "mma.sync.aligned.m16n8k16.row.col.f32.bf16.bf16.f32 "
                                "{%0,%1,%2,%3}, {%4,%5,%6,%7}, {%8,%9}, {%0,%1,%2,%3};"
                                : "+f"(d[mb][2*np+1][0]), "+f"(d[mb][2*np+1][1]),
                                  "+f"(d[mb][2*np+1][2]), "+f"(d[mb][2*np+1][3])
                                : "r"(a[mb][0]), "r"(a[mb][1]), "r"(a[mb][2]), "r"(a[mb][3]),
                                  "r"(b[2]), "r"(b[3]));
                        }
                    }
                }
            }
        }
    }

    // ---- epilogue: per-row online lse + target pick ----
    const int qr = lane >> 2, qc = lane & 3;
    #pragma unroll
    for (int mb = 0; mb < 2; ++mb) {
        #pragma unroll
        for (int half = 0; half < 2; ++half) {
            const int row = wm * 32 + mb * 16 + qr + half * 8;
            const int wil = s_wil[row];
            float m = -INFINITY, s = 0.f, tz = 0.f;
            int fnd = 0;
            #pragma unroll
            for (int nb = 0; nb < 8; ++nb) {
                const int cb = wn * 64 + nb * 8 + qc * 2;
                const float z0 = d[mb][nb][half * 2 + 0];
                const float z1 = d[mb][nb][half * 2 + 1];
                if (cb < vc)     { lse_update(m, s, z0); if (cb == wil)     { tz = z0; fnd = 1; } }
                if (cb + 1 < vc) { lse_update(m, s, z1); if (cb + 1 == wil) { tz = z1; fnd = 1; } }
            }
            #pragma unroll
            for (int off = 1; off <= 2; off <<= 1) {
                const float om = __shfl_xor_sync(0xffffffffu, m, off);
                const float os = __shfl_xor_sync(0xffffffffu, s, off);
                const float otz = __shfl_xor_sync(0xffffffffu, tz, off);
                const int   of  = __shfl_xor_sync(0xffffffffu, fnd, off);
                const float nm = fmaxf(m, om);
                s = s * expf(m - nm) + os * expf(om - nm);
                m = nm;
                if (of) { tz = otz; fnd = 1; }
            }
            if (qc == 0) {
                s_pm[wn][row] = m;  s_ps[wn][row] = s;
                s_ptz[wn][row] = tz; s_pf[wn][row] = fnd;
            }
        }
    }
    __syncthreads();

    if (tid < MTILE) {
        const int idx = s_idx[tid];
        if (idx >= 0) {
            const float m0 = s_pm[0][tid], s0 = s_ps[0][tid];
            const float m1 = s_pm[1][tid], s1 = s_ps[1][tid];
            const float nm = fmaxf(m0, m1);
            const float sc = s0 * expf(m0 - nm) + s1 * expf(m1 - nm);
            g_pm[idx * NCT + nt] = nm;
            g_ps[idx * NCT + nt] = sc;
            if (s_pf[0][tid])      g_tz[idx] = s_ptz[0][tid];
            else if (s_pf[1][tid]) g_tz[idx] = s_ptz[1][tid];
        }
    }
}

// ---------------- Kernel D: combine (warp per token) + g_cnt reset ----------------
__global__ void __launch_bounds__(256)
combine_kernel(float* __restrict__ out)
{
    const int tid = threadIdx.x;
    const int n = blockIdx.x * 8 + (tid >> 5);
    const int lane = tid & 31;
    float m = -1e30f, s = 0.f;
    if (lane < NCT) { m = g_pm[n * NCT + lane]; s = g_ps[n * NCT + lane]; }
    #pragma unroll
    for (int off = 16; off; off >>= 1) {
        const float om = __shfl_xor_sync(0xffffffffu, m, off);
        const float os = __shfl_xor_sync(0xffffffffu, s, off);
        const float nm = fmaxf(m, om);
        s = s * expf(m - nm) + os * expf(om - nm);
        m = nm;
    }
    if (lane == 0)
        out[n] = -g_head[n] - (g_tz[n] - (m + logf(s)));
    if (blockIdx.x == 0 && tid < K_CL) g_cnt[tid] = 0;   // reset for next replay
}

extern "C" void kernel_launch(void* const* d_in, const int* in_sizes, int n_in,
                              void* d_out, int out_size)
{
    const float* x      = (const float*)d_in[0];
    const int*   y      = (const int*)  d_in[1];
    const int*   y_pos  = (const int*)  d_in[2];
    const float* cw     = (const float*)d_in[5];
    const float* logits = (const float*)d_in[6];
    float* out = (float*)d_out;

    cudaFuncSetAttribute(head_kernel,
                         cudaFuncAttributeMaxDynamicSharedMemorySize, HEAD_SMEM);
    cudaFuncSetAttribute(tail_mma_kernel,
                         cudaFuncAttributeMaxDynamicSharedMemorySize, TAIL_DSMEM);

    head_kernel<<<256, 256, HEAD_SMEM>>>(x, y, y_pos, cw);
    tail_mma_kernel<<<dim3(K_CL, NCT), 512, TAIL_DSMEM>>>(logits);
    combine_kernel<<<256, 256>>>(out);
}

// round 17
// speedup vs baseline: 1.3494x; 1.3494x over previous
#include <cuda_runtime.h>
#include <cuda_bf16.h>
#include <math.h>

#define N_TOK 2048
#define H_DIM 1024
#define V_DIM 50304
#define K_CL  16
#define C_CL  3144
#define NTILE 128
#define NCT   25            // 24 full n-tiles + 72-col tail
#define VTAIL 72
#define KC    32            // K per chunk
#define NCH   (H_DIM / KC)  // 32 chunks
#define ASTR  40            // A smem row stride (bf16): 32 + 8 pad
#define BSTR  136           // B smem k-row stride (bf16): 128 + 8 pad
#define HSTR  1028
#define HEAD_SMEM (K_CL * HSTR * 4)     // 65792 B

__device__ float g_head[N_TOK];
__device__ int   g_within[N_TOK];
__device__ int   g_cnt[K_CL];            // zeroed at load + reset by combine_kernel
__device__ int   g_list[K_CL * N_TOK];
__device__ float g_pm[N_TOK * NCT];
__device__ float g_ps[N_TOK * NCT];
__device__ float g_tz[N_TOK];
__device__ __nv_bfloat16 g_xbf[K_CL * 256 * H_DIM];  // 16 clusters x 256 rows, 8MB

__device__ __forceinline__ unsigned smem_u32(const void* p) {
    unsigned a;
    asm("{ .reg .u64 t; cvta.to.shared.u64 t, %1; cvt.u32.u64 %0, t; }"
        : "=r"(a) : "l"(p));
    return a;
}
__device__ __forceinline__ void cpa16(unsigned dst, const void* src) {
    asm volatile("cp.async.cg.shared.global [%0], [%1], 16;"
                 :: "r"(dst), "l"(src) : "memory");
}
#define CP_COMMIT() asm volatile("cp.async.commit_group;" ::: "memory")
#define CP_WAIT0()  asm volatile("cp.async.wait_group 0;" ::: "memory")
__device__ __forceinline__ void lse_update(float &m, float &s, float z) {
    if (z <= m) { s += expf(z - m); }
    else        { s = s * expf(m - z) + 1.f; m = z; }
}

// ---------------- Kernel A: head log-softmax + bucketing + bf16 x-scatter ----------------
// 256 CTAs, one token per warp. cw transposed into smem once per CTA.
__global__ void __launch_bounds__(256)
head_kernel(const float* __restrict__ x, const int* __restrict__ y,
            const int* __restrict__ y_pos, const float* __restrict__ cw)
{
    extern __shared__ float cwt[];               // [16][HSTR]
    const int tid = threadIdx.x, lane = tid & 31, wid = tid >> 5;

    const float4* cw4 = reinterpret_cast<const float4*>(cw);
    #pragma unroll
    for (int it = 0; it < 16; ++it) {
        const int j = it * 256 + tid;            // float4 index in [0,4096)
        const float4 v = __ldg(cw4 + j);
        const int h = j >> 2, k0 = (j & 3) * 4;
        cwt[(k0 + 0) * HSTR + h] = v.x;
        cwt[(k0 + 1) * HSTR + h] = v.y;
        cwt[(k0 + 2) * HSTR + h] = v.z;
        cwt[(k0 + 3) * HSTR + h] = v.w;
    }
    __syncthreads();

    const int n = blockIdx.x * 8 + wid;
    const float* xr = x + (size_t)n * H_DIM;
    const float4* xr4 = reinterpret_cast<const float4*>(xr);

    float a[K_CL];
    #pragma unroll
    for (int kk = 0; kk < K_CL; ++kk) a[kk] = 0.f;

    #pragma unroll 2
    for (int qb = 0; qb < 8; ++qb) {
        const int h0 = qb * 128 + lane * 4;
        const float4 xv = __ldg(xr4 + (h0 >> 2));
        #pragma unroll
        for (int kk = 0; kk < K_CL; ++kk) {
            const float4 w = *reinterpret_cast<const float4*>(&cwt[kk * HSTR + h0]);
            a[kk] = fmaf(xv.x, w.x, fmaf(xv.y, w.y, fmaf(xv.z, w.z,
                     fmaf(xv.w, w.w, a[kk]))));
        }
    }
    #pragma unroll
    for (int kk = 0; kk < K_CL; ++kk)
        #pragma unroll
        for (int off = 16; off; off >>= 1)
            a[kk] += __shfl_xor_sync(0xffffffffu, a[kk], off);

    const int yp = y_pos[n];
    int p = 0;
    if (lane == 0) {
        float m = a[0];
        #pragma unroll
        for (int kk = 1; kk < K_CL; ++kk) m = fmaxf(m, a[kk]);
        float e = 0.f;
        #pragma unroll
        for (int kk = 0; kk < K_CL; ++kk) e += expf(a[kk] - m);
        float s = a[0];
        #pragma unroll
        for (int kk = 0; kk < K_CL; ++kk) if (kk == yp) s = a[kk];
        g_head[n]   = s - m - logf(e);
        g_within[n] = y[n] % C_CL;            // token_in_pos_id[i][v] == v % C
        p = atomicAdd(&g_cnt[yp], 1);
        g_list[yp * N_TOK + p] = n;           // order nondeterministic; output order-invariant
    }
    p = __shfl_sync(0xffffffffu, p, 0);

    if (p < 256) {
        __nv_bfloat16* dst = g_xbf + (size_t)(yp * 256 + p) * H_DIM;
        #pragma unroll
        for (int q = 0; q < 4; ++q) {
            const int h8 = q * 256 + lane * 8;
            const float4 v0 = __ldg(xr4 + (h8 >> 2));
            const float4 v1 = __ldg(xr4 + (h8 >> 2) + 1);
            __nv_bfloat162 p0 = __floats2bfloat162_rn(v0.x, v0.y);
            __nv_bfloat162 p1 = __floats2bfloat162_rn(v0.z, v0.w);
            __nv_bfloat162 p2 = __floats2bfloat162_rn(v1.x, v1.y);
            __nv_bfloat162 p3 = __floats2bfloat162_rn(v1.z, v1.w);
            uint4 u;
            u.x = *reinterpret_cast<unsigned*>(&p0);
            u.y = *reinterpret_cast<unsigned*>(&p1);
            u.z = *reinterpret_cast<unsigned*>(&p2);
            u.w = *reinterpret_cast<unsigned*>(&p3);
            *reinterpret_cast<uint4*>(dst + h8) = u;
        }
    }
}

// ---------------- Kernel C: bf16 mma.sync tail GEMM + lse partials ----------------
// grid (K_CL, 2, NCT). CTA: M=128, N=128, K=1024. 8 warps = 4(M) x 2(N).
// 2 CTAs/SM; double-buffered smem, one sync/chunk; A via cp.async from g_xbf.
// Fully-invalid warps (mt=1 partial CTAs) skip ALL ldmatrix+MMA work.
__global__ void __launch_bounds__(256, 2)
tail_mma_kernel(const float* __restrict__ logits)
{
    __shared__ __align__(16) __nv_bfloat16 As[2][NTILE * ASTR];
    __shared__ __align__(16) __nv_bfloat16 Bs[2][KC * BSTR];
    __shared__ int   s_idx[128], s_wil[128];
    __shared__ float s_pm[2][128], s_ps[2][128], s_ptz[2][128];
    __shared__ int   s_pf[2][128];

    const int k  = blockIdx.x;
    const int mt = blockIdx.y;
    const int nt = blockIdx.z;
    const int cnt = g_cnt[k];
    const int start = mt * 128;
    if (start >= cnt) return;
    const int tid = threadIdx.x, wid = tid >> 5, lane = tid & 31;
    const int vc  = (nt == NCT - 1) ? VTAIL : NTILE;
    const int ntb = nt * NTILE;
    const int rows_valid = min(128, cnt - start);
    const float* gW = logits + (size_t)k * C_CL + ntb;
    const __nv_bfloat16* gx = g_xbf + (size_t)(k * 256 + mt * 128) * H_DIM;

    if (tid < 128) {
        const int idx = (start + tid < cnt) ? g_list[k * N_TOK + start + tid] : -1;
        s_idx[tid] = idx;
        s_wil[tid] = (idx >= 0) ? (g_within[idx] - ntb) : (int)0xC0000000;
    }
    __syncthreads();

    const int arow0 = tid >> 2, aseg = tid & 3;
    const unsigned aoff = arow0 * 80 + aseg * 16;
    const __nv_bfloat16* asrc = gx + (size_t)arow0 * H_DIM + aseg * 8;

    const int bc4 = lane * 4;
    const int br0 = tid >> 5;
    const bool bvalid = bc4 < vc;
    const float* bbase = gW + (size_t)br0 * V_DIM + bc4;
    const unsigned bsts0 = br0 * BSTR + bc4;

    {
        const unsigned ab = smem_u32(&As[0][0]);
        cpa16(ab + aoff, asrc);
        cpa16(ab + aoff + 64 * 80, asrc + 64 * H_DIM);
        CP_COMMIT();
    }
    float4 rb[4];
    #pragma unroll
    for (int it = 0; it < 4; ++it)
        rb[it] = bvalid ? *reinterpret_cast<const float4*>(bbase + (size_t)it * 8 * V_DIM)
                        : make_float4(0.f, 0.f, 0.f, 0.f);

    float d[2][8][4];
    #pragma unroll
    for (int mb = 0; mb < 2; ++mb)
        #pragma unroll
        for (int nb = 0; nb < 8; ++nb)
            #pragma unroll
            for (int j = 0; j < 4; ++j) d[mb][nb][j] = 0.f;

    const int wm = wid >> 1, wn = wid & 1;
    const bool mbv[2] = { wm * 32 < rows_valid, wm * 32 + 16 < rows_valid };
    const bool wactive = mbv[0];                 // mbv[1] implies mbv[0]

    for (int c = 0; c < NCH; ++c) {
        const int buf = c & 1;
        #pragma unroll
        for (int it = 0; it < 4; ++it) {
            __nv_bfloat162 p0 = __floats2bfloat162_rn(rb[it].x, rb[it].y);
            __nv_bfloat162 p1 = __floats2bfloat162_rn(rb[it].z, rb[it].w);
            uint2 u;
            u.x = *reinterpret_cast<unsigned*>(&p0);
            u.y = *reinterpret_cast<unsigned*>(&p1);
            *reinterpret_cast<uint2*>(&Bs[buf][bsts0 + it * 8 * BSTR]) = u;
        }
        CP_WAIT0();
        __syncthreads();

        if (c + 1 < NCH) {
            const unsigned ab = smem_u32(&As[buf ^ 1][0]);
            const __nv_bfloat16* as = asrc + (c + 1) * KC;
            cpa16(ab + aoff, as);
            cpa16(ab + aoff + 64 * 80, as + 64 * H_DIM);
            CP_COMMIT();
            const float* bs = bbase + (size_t)(c + 1) * KC * V_DIM;
            #pragma unroll
            for (int it = 0; it < 4; ++it)
                rb[it] = bvalid ? *reinterpret_cast<const float4*>(bs + (size_t)it * 8 * V_DIM)
                                : make_float4(0.f, 0.f, 0.f, 0.f);
        }

        if (wactive) {
            #pragma unroll
            for (int ks = 0; ks < 2; ++ks) {
                const int k0 = ks * 16;
                unsigned a[2][4];
                #pragma unroll
                for (int mb = 0; mb < 2; ++mb) {
                    if (mbv[mb]) {
                        const unsigned addr = smem_u32(
                            &As[buf][(wm * 32 + mb * 16 + (lane & 15)) * ASTR + k0 + ((lane >> 4) << 3)]);
                        asm volatile("ldmatrix.sync.aligned.m8n8.x4.shared.b16 {%0,%1,%2,%3}, [%4];"
                            : "=r"(a[mb][0]), "=r"(a[mb][1]), "=r"(a[mb][2]), "=r"(a[mb][3])
                            : "r"(addr));
                    }
                }
                #pragma unroll
                for (int np = 0; np < 4; ++np) {
                    unsigned b[4];
                    const unsigned addr = smem_u32(
                        &Bs[buf][(k0 + (lane & 15)) * BSTR + wn * 64 + np * 16 + ((lane >> 4) << 3)]);
                    asm volatile("ldmatrix.sync.aligned.m8n8.x4.trans.shared.b16 {%0,%1,%2,%3}, [%4];"
                        : "=r"(b[0]), "=r"(b[1]), "=r"(b[2]), "=r"(b[3]) : "r"(addr));
                    #pragma unroll
                    for (int mb = 0; mb < 2; ++mb) {
                        if (mbv[mb]) {
                            asm volatile(
                                "mma.sync.aligned.m16n8k16.row.col.f32.bf16.bf16.f32 "
                                "{%0,%1,%2,%3}, {%4,%5,%6,%7}, {%8,%9}, {%0,%1,%2,%3};"
                                : "+f"(d[mb][2*np][0]), "+f"(d[mb][2*np][1]),
                                  "+f"(d[mb][2*np][2]), "+f"(d[mb][2*np][3])
                                : "r"(a[mb][0]), "r"(a[mb][1]), "r"(a[mb][2]), "r"(a[mb][3]),
                                  "r"(b[0]), "r"(b[1]));
                            asm volatile(
                                "mma.sync.aligned.m16n8k16.row.col.f32.bf16.bf16.f32 "
                                "{%0,%1,%2,%3}, {%4,%5,%6,%7}, {%8,%9}, {%0,%1,%2,%3};"
                                : "+f"(d[mb][2*np+1][0]), "+f"(d[mb][2*np+1][1]),
                                  "+f"(d[mb][2*np+1][2]), "+f"(d[mb][2*np+1][3])
                                : "r"(a[mb][0]), "r"(a[mb][1]), "r"(a[mb][2]), "r"(a[mb][3]),
                                  "r"(b[2]), "r"(b[3]));
                        }
                    }
                }
            }
        }
    }

    // ---- epilogue: per-row online lse + target pick ----
    const int qr = lane >> 2, qc = lane & 3;
    #pragma unroll
    for (int mb = 0; mb < 2; ++mb) {
        #pragma unroll
        for (int half = 0; half < 2; ++half) {
            const int row = wm * 32 + mb * 16 + qr + half * 8;
            const int wil = s_wil[row];
            float m = -INFINITY, s = 0.f, tz = 0.f;
            int fnd = 0;
            #pragma unroll
            for (int nb = 0; nb < 8; ++nb) {
                const int cb = wn * 64 + nb * 8 + qc * 2;
                const float z0 = d[mb][nb][half * 2 + 0];
                const float z1 = d[mb][nb][half * 2 + 1];
                if (cb < vc)     { lse_update(m, s, z0); if (cb == wil)     { tz = z0; fnd = 1; } }
                if (cb + 1 < vc) { lse_update(m, s, z1); if (cb + 1 == wil) { tz = z1; fnd = 1; } }
            }
            #pragma unroll
            for (int off = 1; off <= 2; off <<= 1) {
                const float om = __shfl_xor_sync(0xffffffffu, m, off);
                const float os = __shfl_xor_sync(0xffffffffu, s, off);
                const float otz = __shfl_xor_sync(0xffffffffu, tz, off);
                const int   of  = __shfl_xor_sync(0xffffffffu, fnd, off);
                const float nm = fmaxf(m, om);
                s = s * expf(m - nm) + os * expf(om - nm);
                m = nm;
                if (of) { tz = otz; fnd = 1; }
            }
            if (qc == 0) {
                s_pm[wn][row] = m;  s_ps[wn][row] = s;
                s_ptz[wn][row] = tz; s_pf[wn][row] = fnd;
            }
        }
    }
    __syncthreads();

    if (tid < 128) {
        const int idx = s_idx[tid];
        if (idx >= 0) {
            const float m0 = s_pm[0][tid], s0 = s_ps[0][tid];
            const float m1 = s_pm[1][tid], s1 = s_ps[1][tid];
            const float nm = fmaxf(m0, m1);
            const float sc = s0 * expf(m0 - nm) + s1 * expf(m1 - nm);
            g_pm[idx * NCT + nt] = nm;
            g_ps[idx * NCT + nt] = sc;
            if (s_pf[0][tid])      g_tz[idx] = s_ptz[0][tid];
            else if (s_pf[1][tid]) g_tz[idx] = s_ptz[1][tid];
        }
    }
}

// ---------------- Kernel D: combine (warp per token) + g_cnt reset ----------------
__global__ void __launch_bounds__(256)
combine_kernel(float* __restrict__ out)
{
    const int tid = threadIdx.x;
    const int n = blockIdx.x * 8 + (tid >> 5);
    const int lane = tid & 31;
    float m = -1e30f, s = 0.f;
    if (lane < NCT) { m = g_pm[n * NCT + lane]; s = g_ps[n * NCT + lane]; }
    #pragma unroll
    for (int off = 16; off; off >>= 1) {
        const float om = __shfl_xor_sync(0xffffffffu, m, off);
        const float os = __shfl_xor_sync(0xffffffffu, s, off);
        const float nm = fmaxf(m, om);
        s = s * expf(m - nm) + os * expf(om - nm);
        m = nm;
    }
    if (lane == 0)
        out[n] = -g_head[n] - (g_tz[n] - (m + logf(s)));
    if (blockIdx.x == 0 && tid < K_CL) g_cnt[tid] = 0;   // reset for next replay
}

extern "C" void kernel_launch(void* const* d_in, const int* in_sizes, int n_in,
                              void* d_out, int out_size)
{
    const float* x      = (const float*)d_in[0];
    const int*   y      = (const int*)  d_in[1];
    const int*   y_pos  = (const int*)  d_in[2];
    const float* cw     = (const float*)d_in[5];
    const float* logits = (const float*)d_in[6];
    float* out = (float*)d_out;

    cudaFuncSetAttribute(head_kernel,
                         cudaFuncAttributeMaxDynamicSharedMemorySize, HEAD_SMEM);

    head_kernel<<<256, 256, HEAD_SMEM>>>(x, y, y_pos, cw);
    tail_mma_kernel<<<dim3(K_CL, 2, NCT), 256>>>(logits);
    combine_kernel<<<256, 256>>>(out);
}